// round 4
// baseline (speedup 1.0000x reference)
#include <cuda_runtime.h>
#include <cuda_fp16.h>
#include <math.h>

#define NMAX 50000
#define MMAX 800000
#define DD 256

// ---------------- scratch (static device globals; no allocation) ----------------
__device__ __align__(16) __half g_Q[(size_t)NMAX * DD];
__device__ __align__(16) __half g_K[(size_t)NMAX * DD];
__device__ __align__(16) __half g_V[(size_t)NMAX * DD];
__device__ __align__(16) float  g_att[(size_t)MMAX * 8];   // qk logits
__device__ __align__(16) float  g_sums[(size_t)NMAX * 8];  // segment sums per (node, head)
__device__ __align__(16) float  g_agg[(size_t)NMAX * DD];  // scatter-add target (fp32)
__device__ __align__(16) float  g_h1[(size_t)NMAX * DD];   // hidden after Wagg
__device__ int g_maxbits;

__device__ __forceinline__ int f2ord(float f) {
    int b = __float_as_int(f);
    return b >= 0 ? b : (b ^ 0x7FFFFFFF);
}
__device__ __forceinline__ float ord2f(int b) {
    return __int_as_float(b >= 0 ? b : (b ^ 0x7FFFFFFF));
}

__device__ __forceinline__ unsigned f2tf32(float f) {
    unsigned u;
    asm("cvt.rna.tf32.f32 %0, %1;" : "=r"(u) : "f"(f));
    return u;
}

__device__ __forceinline__ void mma_tf32(float* c, unsigned a0, unsigned a1,
                                         unsigned a2, unsigned a3,
                                         unsigned b0, unsigned b1) {
    asm volatile(
        "mma.sync.aligned.m16n8k8.row.col.f32.tf32.tf32.f32 "
        "{%0,%1,%2,%3}, {%4,%5,%6,%7}, {%8,%9}, {%0,%1,%2,%3};"
        : "+f"(c[0]), "+f"(c[1]), "+f"(c[2]), "+f"(c[3])
        : "r"(a0), "r"(a1), "r"(a2), "r"(a3), "r"(b0), "r"(b1));
}

// ---------------- init ----------------
__global__ void init_kernel(int n4_agg, int n4_sums) {
    int i = blockIdx.x * blockDim.x + threadIdx.x;
    float4 z = make_float4(0.f, 0.f, 0.f, 0.f);
    if (i < n4_agg)  ((float4*)g_agg)[i]  = z;
    if (i < n4_sums) ((float4*)g_sums)[i] = z;
    if (i == 0) g_maxbits = 0x80000000;
}

// ---------------- TF32 tensor-core GEMM ----------------
// C (nrows x 256) = act( actin(A) @ W + b ) [+ res]; C fp32 or fp16
struct GemmSet { const float* W; const float* b; void* C; };

#define AS_STRIDE 36   // [m=128][k=32+4pad]
#define WS_STRIDE 136  // [k=32][n=128+8pad]

template<bool RELU_IN, bool RELU_OUT, bool ADD_RES, bool OUT_HALF>
__global__ __launch_bounds__(256)
void gemm_tc(const float* __restrict__ A,
             GemmSet s0, GemmSet s1, GemmSet s2,
             const float* __restrict__ res, int nrows)
{
    __shared__ __align__(16) unsigned As[128 * AS_STRIDE];
    __shared__ __align__(16) unsigned Ws[32 * WS_STRIDE];

    const GemmSet gs = (blockIdx.z == 0) ? s0 : (blockIdx.z == 1) ? s1 : s2;
    const float* __restrict__ W    = gs.W;
    const float* __restrict__ bias = gs.b;

    const int tid  = threadIdx.x;
    const int lane = tid & 31;
    const int warp = tid >> 5;
    const int wm   = warp >> 2;
    const int wn   = warp & 3;
    const int m0   = blockIdx.x * 128;
    const int n0   = blockIdx.y * 128;

    float acc[4][4][4];
#pragma unroll
    for (int i = 0; i < 4; i++)
#pragma unroll
        for (int j = 0; j < 4; j++)
#pragma unroll
            for (int k = 0; k < 4; k++) acc[i][j][k] = 0.f;

#pragma unroll 1
    for (int kt = 0; kt < 8; ++kt) {
        const int k0 = kt * 32;
#pragma unroll
        for (int it = 0; it < 4; ++it) {
            int idx = it * 256 + tid;
            int row = idx >> 3;
            int kv  = idx & 7;
            int gm  = m0 + row;
            float4 v = make_float4(0.f, 0.f, 0.f, 0.f);
            if (gm < nrows) v = *(const float4*)(A + (size_t)gm * 256 + k0 + kv * 4);
            if (RELU_IN) {
                v.x = fmaxf(v.x, 0.f); v.y = fmaxf(v.y, 0.f);
                v.z = fmaxf(v.z, 0.f); v.w = fmaxf(v.w, 0.f);
            }
            uint4 u = make_uint4(f2tf32(v.x), f2tf32(v.y), f2tf32(v.z), f2tf32(v.w));
            *(uint4*)(As + row * AS_STRIDE + kv * 4) = u;
        }
#pragma unroll
        for (int it = 0; it < 4; ++it) {
            int idx = it * 256 + tid;
            int kr  = idx >> 5;
            int nv  = idx & 31;
            float4 v = *(const float4*)(W + (size_t)(k0 + kr) * 256 + n0 + nv * 4);
            uint4 u = make_uint4(f2tf32(v.x), f2tf32(v.y), f2tf32(v.z), f2tf32(v.w));
            *(uint4*)(Ws + kr * WS_STRIDE + nv * 4) = u;
        }
        __syncthreads();

#pragma unroll
        for (int ks = 0; ks < 4; ++ks) {
            const int kk = ks * 8;
            unsigned af[4][4];
#pragma unroll
            for (int mt = 0; mt < 4; ++mt) {
                int r = wm * 64 + mt * 16 + (lane >> 2);
                int kc = kk + (lane & 3);
                af[mt][0] = As[r * AS_STRIDE + kc];
                af[mt][1] = As[(r + 8) * AS_STRIDE + kc];
                af[mt][2] = As[r * AS_STRIDE + kc + 4];
                af[mt][3] = As[(r + 8) * AS_STRIDE + kc + 4];
            }
            unsigned bf[4][2];
#pragma unroll
            for (int nt = 0; nt < 4; ++nt) {
                int n = wn * 32 + nt * 8 + (lane >> 2);
                bf[nt][0] = Ws[(kk + (lane & 3)) * WS_STRIDE + n];
                bf[nt][1] = Ws[(kk + 4 + (lane & 3)) * WS_STRIDE + n];
            }
#pragma unroll
            for (int mt = 0; mt < 4; ++mt)
#pragma unroll
                for (int nt = 0; nt < 4; ++nt)
                    mma_tf32(acc[mt][nt], af[mt][0], af[mt][1], af[mt][2], af[mt][3],
                             bf[nt][0], bf[nt][1]);
        }
        __syncthreads();
    }

#pragma unroll
    for (int mt = 0; mt < 4; ++mt) {
#pragma unroll
        for (int nt = 0; nt < 4; ++nt) {
            int c  = n0 + wn * 32 + nt * 8 + 2 * (lane & 3);
            float2 b = *(const float2*)(bias + c);
            int r0 = m0 + wm * 64 + mt * 16 + (lane >> 2);
#pragma unroll
            for (int h = 0; h < 2; ++h) {
                int gm = r0 + h * 8;
                if (gm < nrows) {
                    float2 o;
                    o.x = acc[mt][nt][h * 2 + 0] + b.x;
                    o.y = acc[mt][nt][h * 2 + 1] + b.y;
                    if (RELU_OUT) { o.x = fmaxf(o.x, 0.f); o.y = fmaxf(o.y, 0.f); }
                    if (ADD_RES) {
                        float2 r = *(const float2*)(res + (size_t)gm * 256 + c);
                        o.x += r.x; o.y += r.y;
                    }
                    if (OUT_HALF) {
                        *(__half2*)((__half*)gs.C + (size_t)gm * 256 + c) =
                            __float22half2_rn(o);
                    } else {
                        *(float2*)((float*)gs.C + (size_t)gm * 256 + c) = o;
                    }
                }
            }
        }
    }
}

// ---------------- edge qk (fp16 gathers): one warp per edge ----------------
__global__ __launch_bounds__(256)
void edge_qk(const int* __restrict__ recv, const int* __restrict__ send, int m)
{
    __shared__ int smax;
    if (threadIdx.x == 0) smax = 0x80000000;
    __syncthreads();

    const int w = (blockIdx.x * blockDim.x + threadIdx.x) >> 5;
    const int lane = threadIdx.x & 31;
    if (w < m) {
        const int r = recv[w];
        const int s = send[w];
        // row = 256 halves = 32 uint4; lane covers dims [8*lane, 8*lane+8) = head lane>>2
        uint4 qu = ((const uint4*)(g_Q + (size_t)r * 256))[lane];
        uint4 ku = ((const uint4*)(g_K + (size_t)s * 256))[lane];
        const __half2* qh = (const __half2*)&qu;
        const __half2* kh = (const __half2*)&ku;
        float sv = 0.f;
#pragma unroll
        for (int i = 0; i < 4; ++i) {
            float2 q = __half22float2(qh[i]);
            float2 k = __half22float2(kh[i]);
            sv = fmaf(q.x, k.x, sv);
            sv = fmaf(q.y, k.y, sv);
        }
        // reduce within 4-lane group -> per-head dot
        sv += __shfl_xor_sync(0xffffffffu, sv, 2);
        sv += __shfl_xor_sync(0xffffffffu, sv, 1);
        if ((lane & 3) == 0) g_att[(size_t)w * 8 + (lane >> 2)] = sv;
        // warp max (sv uniform within each 4-lane group)
        float mx = sv;
        mx = fmaxf(mx, __shfl_xor_sync(0xffffffffu, mx, 4));
        mx = fmaxf(mx, __shfl_xor_sync(0xffffffffu, mx, 8));
        mx = fmaxf(mx, __shfl_xor_sync(0xffffffffu, mx, 16));
        if (lane == 0) atomicMax(&smax, f2ord(mx));
    }
    __syncthreads();
    if (threadIdx.x == 0) atomicMax(&g_maxbits, smax);
}

// ---------------- segment sums: exp + atomic add (no att write-back) ----------------
__global__ __launch_bounds__(256)
void edge_sums(const int* __restrict__ recv, int m)
{
    __shared__ float sscale;
    if (threadIdx.x == 0) sscale = 3.0f / ord2f(g_maxbits);
    __syncthreads();
    const float scale = sscale;

    int tid = blockIdx.x * blockDim.x + threadIdx.x;
    if (tid >= m * 8) return;
    int e = tid >> 3;
    int h = tid & 7;
    float a = expf(g_att[tid] * scale);
    atomicAdd(&g_sums[(size_t)recv[e] * 8 + h], a);
}

__device__ __forceinline__ void red_add_v4(float* p, float4 v) {
    asm volatile("red.global.add.v4.f32 [%0], {%1,%2,%3,%4};"
                 :: "l"(p), "f"(v.x), "f"(v.y), "f"(v.z), "f"(v.w) : "memory");
}

// ---------------- weighted message scatter (fp16 V gather): warp per edge ----------------
__global__ __launch_bounds__(256)
void edge_msg(const int* __restrict__ recv, const int* __restrict__ send, int m)
{
    __shared__ float sscale;
    if (threadIdx.x == 0) sscale = 3.0f / ord2f(g_maxbits);
    __syncthreads();
    const float scale = sscale;

    const int w = (blockIdx.x * blockDim.x + threadIdx.x) >> 5;
    const int lane = threadIdx.x & 31;
    if (w >= m) return;
    const int r = recv[w];
    const int s = send[w];
    const int h = lane >> 2;

    float logit = g_att[(size_t)w * 8 + h];
    float denom = g_sums[(size_t)r * 8 + h];
    float wv = expf(logit * scale) / (denom * 5.656854249492381f);  // sqrt(32)

    uint4 vu = ((const uint4*)(g_V + (size_t)s * 256))[lane];
    const __half2* vh = (const __half2*)&vu;
    float* Ar = g_agg + (size_t)r * 256 + lane * 8;

    float2 v0 = __half22float2(vh[0]);
    float2 v1 = __half22float2(vh[1]);
    float2 v2 = __half22float2(vh[2]);
    float2 v3 = __half22float2(vh[3]);
    red_add_v4(Ar,     make_float4(v0.x * wv, v0.y * wv, v1.x * wv, v1.y * wv));
    red_add_v4(Ar + 4, make_float4(v2.x * wv, v2.y * wv, v3.x * wv, v3.y * wv));
}

// ---------------- launch ----------------
extern "C" void kernel_launch(void* const* d_in, const int* in_sizes, int n_in,
                              void* d_out, int out_size)
{
    const float* x    = (const float*)d_in[0];
    const int*   ei   = (const int*)d_in[1];
    const float* Wk   = (const float*)d_in[2];
    const float* bk   = (const float*)d_in[3];
    const float* Wq   = (const float*)d_in[4];
    const float* bq   = (const float*)d_in[5];
    const float* Wv   = (const float*)d_in[6];
    const float* bv   = (const float*)d_in[7];
    const float* Wagg = (const float*)d_in[8];
    const float* bagg = (const float*)d_in[9];
    const float* Wff  = (const float*)d_in[10];
    const float* bff  = (const float*)d_in[11];
    float* out = (float*)d_out;

    const int n = in_sizes[0] / 256;
    const int m = in_sizes[1] / 2;
    const int* recv = ei;
    const int* send = ei + m;

    void *Qp, *Kp, *Vp;
    float *aggp, *h1p;
    cudaGetSymbolAddress(&Qp, g_Q);
    cudaGetSymbolAddress(&Kp, g_K);
    cudaGetSymbolAddress(&Vp, g_V);
    cudaGetSymbolAddress((void**)&aggp, g_agg);
    cudaGetSymbolAddress((void**)&h1p,  g_h1);

    const int n4_agg  = n * 64;
    const int n4_sums = n * 2;
    init_kernel<<<(n4_agg + 255) / 256, 256>>>(n4_agg, n4_sums);

    const int gx = (n + 127) / 128;

    GemmSet sq = {Wq, bq, Qp};
    GemmSet sk = {Wk, bk, Kp};
    GemmSet sv = {Wv, bv, Vp};
    gemm_tc<false, false, false, true><<<dim3(gx, 2, 3), 256>>>(x, sq, sk, sv, nullptr, n);

    edge_qk<<<(m + 7) / 8, 256>>>(recv, send, m);
    edge_sums<<<(m * 8 + 255) / 256, 256>>>(recv, m);
    edge_msg<<<(m + 7) / 8, 256>>>(recv, send, m);

    GemmSet sa = {Wagg, bagg, h1p};
    gemm_tc<true, true, false, false><<<dim3(gx, 2, 1), 256>>>(aggp, sa, sa, sa, nullptr, n);
    GemmSet sf = {Wff, bff, out};
    gemm_tc<false, true, true, false><<<dim3(gx, 2, 1), 256>>>(h1p, sf, sf, sf, x, n);
}

// round 5
// speedup vs baseline: 1.1773x; 1.1773x over previous
#include <cuda_runtime.h>
#include <cuda_fp16.h>
#include <math.h>

#define NMAX 50000
#define MMAX 800000
#define DD 256

// ---------------- scratch (static device globals; no allocation) ----------------
__device__ __align__(16) __half g_Q[(size_t)NMAX * DD];
__device__ __align__(16) __half g_K[(size_t)NMAX * DD];
__device__ __align__(16) __half g_V[(size_t)NMAX * DD];
__device__ __align__(16) float  g_att[(size_t)MMAX * 8];   // qk logits (sorted edge order)
__device__ __align__(16) float  g_agg[(size_t)NMAX * DD];  // aggregated messages (fp32)
__device__ __align__(16) float  g_h1[(size_t)NMAX * DD];   // hidden after Wagg
__device__ int g_hist[NMAX];        // per-recv degree
__device__ int g_cursor[NMAX];      // scatter cursor
__device__ int g_rowoff[NMAX + 1];  // CSR row offsets
__device__ int g_send_s[MMAX];      // send idx, sorted by recv
__device__ int g_recv_s[MMAX];      // recv idx, sorted
__device__ int g_maxbits;

__device__ __forceinline__ int f2ord(float f) {
    int b = __float_as_int(f);
    return b >= 0 ? b : (b ^ 0x7FFFFFFF);
}
__device__ __forceinline__ float ord2f(int b) {
    return __int_as_float(b >= 0 ? b : (b ^ 0x7FFFFFFF));
}

__device__ __forceinline__ unsigned f2tf32(float f) {
    unsigned u;
    asm("cvt.rna.tf32.f32 %0, %1;" : "=r"(u) : "f"(f));
    return u;
}

__device__ __forceinline__ void mma_tf32(float* c, unsigned a0, unsigned a1,
                                         unsigned a2, unsigned a3,
                                         unsigned b0, unsigned b1) {
    asm volatile(
        "mma.sync.aligned.m16n8k8.row.col.f32.tf32.tf32.f32 "
        "{%0,%1,%2,%3}, {%4,%5,%6,%7}, {%8,%9}, {%0,%1,%2,%3};"
        : "+f"(c[0]), "+f"(c[1]), "+f"(c[2]), "+f"(c[3])
        : "r"(a0), "r"(a1), "r"(a2), "r"(a3), "r"(b0), "r"(b1));
}

// ---------------- CSR build ----------------
__global__ void init_kernel(int n) {
    int i = blockIdx.x * blockDim.x + threadIdx.x;
    if (i < n) g_hist[i] = 0;
    if (i == 0) g_maxbits = 0x80000000;
}

__global__ void hist_kernel(const int* __restrict__ recv, int m) {
    int i = blockIdx.x * blockDim.x + threadIdx.x;
    if (i < m) atomicAdd(&g_hist[recv[i]], 1);
}

// single-block exclusive scan of g_hist -> g_rowoff, g_cursor
__global__ __launch_bounds__(1024)
void scan_kernel(int n) {
    __shared__ int ssum[1024];
    const int t = threadIdx.x;
    const int chunk = (n + 1023) >> 10;
    const int base = t * chunk;
    const int lim = min(base + chunk, n);
    int s = 0;
    for (int i = base; i < lim; ++i) s += g_hist[i];
    ssum[t] = s;
    __syncthreads();
    // Hillis-Steele inclusive scan
    for (int off = 1; off < 1024; off <<= 1) {
        int v = (t >= off) ? ssum[t - off] : 0;
        __syncthreads();
        ssum[t] += v;
        __syncthreads();
    }
    int run = ssum[t] - s;  // exclusive prefix of this chunk
    for (int i = base; i < lim; ++i) {
        int c = g_hist[i];
        g_rowoff[i] = run;
        g_cursor[i] = run;
        run += c;
    }
    if (t == 1023) g_rowoff[n] = run;
}

__global__ void permute_kernel(const int* __restrict__ recv,
                               const int* __restrict__ send, int m) {
    int e = blockIdx.x * blockDim.x + threadIdx.x;
    if (e >= m) return;
    int r = recv[e];
    int pos = atomicAdd(&g_cursor[r], 1);
    g_send_s[pos] = send[e];
    g_recv_s[pos] = r;
}

// ---------------- TF32 tensor-core GEMM ----------------
struct GemmSet { const float* W; const float* b; void* C; };

#define AS_STRIDE 36
#define WS_STRIDE 136

template<bool RELU_IN, bool RELU_OUT, bool ADD_RES, bool OUT_HALF>
__global__ __launch_bounds__(256)
void gemm_tc(const float* __restrict__ A,
             GemmSet s0, GemmSet s1, GemmSet s2,
             const float* __restrict__ res, int nrows)
{
    __shared__ __align__(16) unsigned As[128 * AS_STRIDE];
    __shared__ __align__(16) unsigned Ws[32 * WS_STRIDE];

    const GemmSet gs = (blockIdx.z == 0) ? s0 : (blockIdx.z == 1) ? s1 : s2;
    const float* __restrict__ W    = gs.W;
    const float* __restrict__ bias = gs.b;

    const int tid  = threadIdx.x;
    const int lane = tid & 31;
    const int warp = tid >> 5;
    const int wm   = warp >> 2;
    const int wn   = warp & 3;
    const int m0   = blockIdx.x * 128;
    const int n0   = blockIdx.y * 128;

    float acc[4][4][4];
#pragma unroll
    for (int i = 0; i < 4; i++)
#pragma unroll
        for (int j = 0; j < 4; j++)
#pragma unroll
            for (int k = 0; k < 4; k++) acc[i][j][k] = 0.f;

#pragma unroll 1
    for (int kt = 0; kt < 8; ++kt) {
        const int k0 = kt * 32;
#pragma unroll
        for (int it = 0; it < 4; ++it) {
            int idx = it * 256 + tid;
            int row = idx >> 3;
            int kv  = idx & 7;
            int gm  = m0 + row;
            float4 v = make_float4(0.f, 0.f, 0.f, 0.f);
            if (gm < nrows) v = *(const float4*)(A + (size_t)gm * 256 + k0 + kv * 4);
            if (RELU_IN) {
                v.x = fmaxf(v.x, 0.f); v.y = fmaxf(v.y, 0.f);
                v.z = fmaxf(v.z, 0.f); v.w = fmaxf(v.w, 0.f);
            }
            uint4 u = make_uint4(f2tf32(v.x), f2tf32(v.y), f2tf32(v.z), f2tf32(v.w));
            *(uint4*)(As + row * AS_STRIDE + kv * 4) = u;
        }
#pragma unroll
        for (int it = 0; it < 4; ++it) {
            int idx = it * 256 + tid;
            int kr  = idx >> 5;
            int nv  = idx & 31;
            float4 v = *(const float4*)(W + (size_t)(k0 + kr) * 256 + n0 + nv * 4);
            uint4 u = make_uint4(f2tf32(v.x), f2tf32(v.y), f2tf32(v.z), f2tf32(v.w));
            *(uint4*)(Ws + kr * WS_STRIDE + nv * 4) = u;
        }
        __syncthreads();

#pragma unroll
        for (int ks = 0; ks < 4; ++ks) {
            const int kk = ks * 8;
            unsigned af[4][4];
#pragma unroll
            for (int mt = 0; mt < 4; ++mt) {
                int r = wm * 64 + mt * 16 + (lane >> 2);
                int kc = kk + (lane & 3);
                af[mt][0] = As[r * AS_STRIDE + kc];
                af[mt][1] = As[(r + 8) * AS_STRIDE + kc];
                af[mt][2] = As[r * AS_STRIDE + kc + 4];
                af[mt][3] = As[(r + 8) * AS_STRIDE + kc + 4];
            }
            unsigned bf[4][2];
#pragma unroll
            for (int nt = 0; nt < 4; ++nt) {
                int n = wn * 32 + nt * 8 + (lane >> 2);
                bf[nt][0] = Ws[(kk + (lane & 3)) * WS_STRIDE + n];
                bf[nt][1] = Ws[(kk + 4 + (lane & 3)) * WS_STRIDE + n];
            }
#pragma unroll
            for (int mt = 0; mt < 4; ++mt)
#pragma unroll
                for (int nt = 0; nt < 4; ++nt)
                    mma_tf32(acc[mt][nt], af[mt][0], af[mt][1], af[mt][2], af[mt][3],
                             bf[nt][0], bf[nt][1]);
        }
        __syncthreads();
    }

#pragma unroll
    for (int mt = 0; mt < 4; ++mt) {
#pragma unroll
        for (int nt = 0; nt < 4; ++nt) {
            int c  = n0 + wn * 32 + nt * 8 + 2 * (lane & 3);
            float2 b = *(const float2*)(bias + c);
            int r0 = m0 + wm * 64 + mt * 16 + (lane >> 2);
#pragma unroll
            for (int h = 0; h < 2; ++h) {
                int gm = r0 + h * 8;
                if (gm < nrows) {
                    float2 o;
                    o.x = acc[mt][nt][h * 2 + 0] + b.x;
                    o.y = acc[mt][nt][h * 2 + 1] + b.y;
                    if (RELU_OUT) { o.x = fmaxf(o.x, 0.f); o.y = fmaxf(o.y, 0.f); }
                    if (ADD_RES) {
                        float2 r = *(const float2*)(res + (size_t)gm * 256 + c);
                        o.x += r.x; o.y += r.y;
                    }
                    if (OUT_HALF) {
                        *(__half2*)((__half*)gs.C + (size_t)gm * 256 + c) =
                            __float22half2_rn(o);
                    } else {
                        *(float2*)((float*)gs.C + (size_t)gm * 256 + c) = o;
                    }
                }
            }
        }
    }
}

// ---------------- edge qk on sorted edges: one warp per edge ----------------
__global__ __launch_bounds__(256)
void edge_qk(int m)
{
    __shared__ int smax;
    if (threadIdx.x == 0) smax = 0x80000000;
    __syncthreads();

    const int w = (blockIdx.x * blockDim.x + threadIdx.x) >> 5;
    const int lane = threadIdx.x & 31;
    if (w < m) {
        const int r = g_recv_s[w];
        const int s = g_send_s[w];
        uint4 qu = ((const uint4*)(g_Q + (size_t)r * 256))[lane];
        uint4 ku = ((const uint4*)(g_K + (size_t)s * 256))[lane];
        const __half2* qh = (const __half2*)&qu;
        const __half2* kh = (const __half2*)&ku;
        float sv = 0.f;
#pragma unroll
        for (int i = 0; i < 4; ++i) {
            float2 q = __half22float2(qh[i]);
            float2 k = __half22float2(kh[i]);
            sv = fmaf(q.x, k.x, sv);
            sv = fmaf(q.y, k.y, sv);
        }
        sv += __shfl_xor_sync(0xffffffffu, sv, 2);
        sv += __shfl_xor_sync(0xffffffffu, sv, 1);
        if ((lane & 3) == 0) g_att[(size_t)w * 8 + (lane >> 2)] = sv;
        float mx = sv;
        mx = fmaxf(mx, __shfl_xor_sync(0xffffffffu, mx, 4));
        mx = fmaxf(mx, __shfl_xor_sync(0xffffffffu, mx, 8));
        mx = fmaxf(mx, __shfl_xor_sync(0xffffffffu, mx, 16));
        if (lane == 0) atomicMax(&smax, f2ord(mx));
    }
    __syncthreads();
    if (threadIdx.x == 0) atomicMax(&g_maxbits, smax);
}

// ---------------- per-node softmax + weighted aggregation: warp per node ----------------
__global__ __launch_bounds__(256)
void node_msg(int n)
{
    __shared__ float sden[8][8];
    __shared__ float sscale;
    if (threadIdx.x == 0) sscale = 3.0f / ord2f(g_maxbits);
    __syncthreads();
    const float scale = sscale;

    const int warp = threadIdx.x >> 5;
    const int lane = threadIdx.x & 31;
    const int v = blockIdx.x * 8 + warp;
    if (v >= n) return;

    const int off = g_rowoff[v];
    const int end = g_rowoff[v + 1];

    // pass 1: denominator per head. lane -> edge off+(lane>>3), head lane&7
    float dsum = 0.f;
    for (int base = off; base < end; base += 4) {
        int e = base + (lane >> 3);
        float a = 0.f;
        if (e < end) a = __expf(g_att[(size_t)e * 8 + (lane & 7)] * scale);
        dsum += a;
    }
    dsum += __shfl_xor_sync(0xffffffffu, dsum, 8);
    dsum += __shfl_xor_sync(0xffffffffu, dsum, 16);
    if (lane < 8) sden[warp][lane] = dsum * 5.656854249492381f;  // fold sqrt(32)
    __syncwarp();

    // pass 2: weighted V aggregation. lane covers dims [8*lane, 8*lane+8), head=lane>>2
    const int h = lane >> 2;
    const float inv = 1.0f / sden[warp][h];
    float acc[8] = {0.f, 0.f, 0.f, 0.f, 0.f, 0.f, 0.f, 0.f};

    int s_next = (off < end) ? g_send_s[off] : 0;
    for (int e = off; e < end; ++e) {
        const int s = s_next;
        if (e + 1 < end) s_next = g_send_s[e + 1];
        float wv = __expf(g_att[(size_t)e * 8 + h] * scale) * inv;
        uint4 vu = ((const uint4*)(g_V + (size_t)s * 256))[lane];
        const __half2* vh = (const __half2*)&vu;
#pragma unroll
        for (int i = 0; i < 4; ++i) {
            float2 f = __half22float2(vh[i]);
            acc[2 * i]     = fmaf(wv, f.x, acc[2 * i]);
            acc[2 * i + 1] = fmaf(wv, f.y, acc[2 * i + 1]);
        }
    }

    float4* Ap = (float4*)(g_agg + (size_t)v * 256 + lane * 8);
    Ap[0] = make_float4(acc[0], acc[1], acc[2], acc[3]);
    Ap[1] = make_float4(acc[4], acc[5], acc[6], acc[7]);
}

// ---------------- launch ----------------
extern "C" void kernel_launch(void* const* d_in, const int* in_sizes, int n_in,
                              void* d_out, int out_size)
{
    const float* x    = (const float*)d_in[0];
    const int*   ei   = (const int*)d_in[1];
    const float* Wk   = (const float*)d_in[2];
    const float* bk   = (const float*)d_in[3];
    const float* Wq   = (const float*)d_in[4];
    const float* bq   = (const float*)d_in[5];
    const float* Wv   = (const float*)d_in[6];
    const float* bv   = (const float*)d_in[7];
    const float* Wagg = (const float*)d_in[8];
    const float* bagg = (const float*)d_in[9];
    const float* Wff  = (const float*)d_in[10];
    const float* bff  = (const float*)d_in[11];
    float* out = (float*)d_out;

    const int n = in_sizes[0] / 256;
    const int m = in_sizes[1] / 2;
    const int* recv = ei;
    const int* send = ei + m;

    void *Qp, *Kp, *Vp;
    float *aggp, *h1p;
    cudaGetSymbolAddress(&Qp, g_Q);
    cudaGetSymbolAddress(&Kp, g_K);
    cudaGetSymbolAddress(&Vp, g_V);
    cudaGetSymbolAddress((void**)&aggp, g_agg);
    cudaGetSymbolAddress((void**)&h1p,  g_h1);

    // CSR build (counting sort by recv)
    init_kernel<<<(n + 255) / 256, 256>>>(n);
    hist_kernel<<<(m + 255) / 256, 256>>>(recv, m);
    scan_kernel<<<1, 1024>>>(n);
    permute_kernel<<<(m + 255) / 256, 256>>>(recv, send, m);

    const int gx = (n + 127) / 128;

    GemmSet sq = {Wq, bq, Qp};
    GemmSet sk = {Wk, bk, Kp};
    GemmSet sv = {Wv, bv, Vp};
    gemm_tc<false, false, false, true><<<dim3(gx, 2, 3), 256>>>(x, sq, sk, sv, nullptr, n);

    edge_qk<<<(m + 7) / 8, 256>>>(m);
    node_msg<<<(n + 7) / 8, 256>>>(n);

    GemmSet sa = {Wagg, bagg, h1p};
    gemm_tc<true, true, false, false><<<dim3(gx, 2, 1), 256>>>(aggp, sa, sa, sa, nullptr, n);
    GemmSet sf = {Wff, bff, out};
    gemm_tc<false, true, true, false><<<dim3(gx, 2, 1), 256>>>(h1p, sf, sf, sf, x, n);
}

// round 6
// speedup vs baseline: 1.4570x; 1.2376x over previous
#include <cuda_runtime.h>
#include <cuda_fp16.h>
#include <math.h>

#define NMAX 50000
#define MMAX 800000
#define DD 256

// ---------------- scratch (static device globals; no allocation) ----------------
__device__ __align__(16) __half g_xh[(size_t)NMAX * DD];   // x in fp16 (GEMM A)
__device__ __align__(16) __half g_Q[(size_t)NMAX * DD];
__device__ __align__(16) __half g_K[(size_t)NMAX * DD];
__device__ __align__(16) __half g_V[(size_t)NMAX * DD];
__device__ __align__(16) __half g_agg[(size_t)NMAX * DD];  // relu'd messages (fp16)
__device__ __align__(16) __half g_h1[(size_t)NMAX * DD];   // relu'd hidden (fp16)
__device__ __align__(16) __half g_WT[5 * 65536];           // weights fp16, [n][k]
__device__ __align__(16) float  g_att[(size_t)MMAX * 8];   // qk logits (sorted order)
__device__ int g_hist[NMAX];
__device__ int g_cursor[NMAX];
__device__ int g_rowoff[NMAX + 1];
__device__ int g_send_s[MMAX];
__device__ int g_recv_s[MMAX];
__device__ int g_maxbits;

__device__ __forceinline__ int f2ord(float f) {
    int b = __float_as_int(f);
    return b >= 0 ? b : (b ^ 0x7FFFFFFF);
}
__device__ __forceinline__ float ord2f(int b) {
    return __int_as_float(b >= 0 ? b : (b ^ 0x7FFFFFFF));
}

__device__ __forceinline__ void mma_f16(float* c, unsigned a0, unsigned a1,
                                        unsigned a2, unsigned a3,
                                        unsigned b0, unsigned b1) {
    asm volatile(
        "mma.sync.aligned.m16n8k16.row.col.f32.f16.f16.f32 "
        "{%0,%1,%2,%3}, {%4,%5,%6,%7}, {%8,%9}, {%0,%1,%2,%3};"
        : "+f"(c[0]), "+f"(c[1]), "+f"(c[2]), "+f"(c[3])
        : "r"(a0), "r"(a1), "r"(a2), "r"(a3), "r"(b0), "r"(b1));
}

// ---------------- CSR build ----------------
__global__ void init_kernel(int n) {
    int i = blockIdx.x * blockDim.x + threadIdx.x;
    if (i < n) g_hist[i] = 0;
    if (i == 0) g_maxbits = 0x80000000;
}

__global__ void hist_kernel(const int* __restrict__ recv, int m) {
    int i = blockIdx.x * blockDim.x + threadIdx.x;
    if (i < m) atomicAdd(&g_hist[recv[i]], 1);
}

__global__ __launch_bounds__(1024)
void scan_kernel(int n) {
    __shared__ int ssum[1024];
    const int t = threadIdx.x;
    const int chunk = (n + 1023) >> 10;
    const int base = t * chunk;
    const int lim = min(base + chunk, n);
    int s = 0;
    for (int i = base; i < lim; ++i) s += g_hist[i];
    ssum[t] = s;
    __syncthreads();
    for (int off = 1; off < 1024; off <<= 1) {
        int v = (t >= off) ? ssum[t - off] : 0;
        __syncthreads();
        ssum[t] += v;
        __syncthreads();
    }
    int run = ssum[t] - s;
    for (int i = base; i < lim; ++i) {
        int c = g_hist[i];
        g_rowoff[i] = run;
        g_cursor[i] = run;
        run += c;
    }
    if (t == 1023) g_rowoff[n] = run;
}

__global__ void permute_kernel(const int* __restrict__ recv,
                               const int* __restrict__ send, int m) {
    int e = blockIdx.x * blockDim.x + threadIdx.x;
    if (e >= m) return;
    int r = recv[e];
    int pos = atomicAdd(&g_cursor[r], 1);
    g_send_s[pos] = send[e];
    g_recv_s[pos] = r;
}

// ---------------- conversions ----------------
__global__ void conv_x(const float* __restrict__ x, int n4) {
    int i = blockIdx.x * blockDim.x + threadIdx.x;
    if (i >= n4) return;
    float4 v = ((const float4*)x)[i];
    __half2 h0 = __floats2half2_rn(v.x, v.y);
    __half2 h1 = __floats2half2_rn(v.z, v.w);
    ((__half2*)g_xh)[2 * i]     = h0;
    ((__half2*)g_xh)[2 * i + 1] = h1;
}

// transpose + fp16: W[k][n] fp32 -> g_WT[z][n][k] fp16. grid (8,8,5), block 32x32.
__global__ void conv_w(const float* w0, const float* w1, const float* w2,
                       const float* w3, const float* w4) {
    __shared__ float t[32][33];
    const float* W = (blockIdx.z == 0) ? w0 : (blockIdx.z == 1) ? w1 :
                     (blockIdx.z == 2) ? w2 : (blockIdx.z == 3) ? w3 : w4;
    int k0 = blockIdx.y * 32, n0 = blockIdx.x * 32;
    t[threadIdx.y][threadIdx.x] = W[(size_t)(k0 + threadIdx.y) * 256 + n0 + threadIdx.x];
    __syncthreads();
    g_WT[(size_t)blockIdx.z * 65536 + (size_t)(n0 + threadIdx.y) * 256 + k0 + threadIdx.x] =
        __float2half_rn(t[threadIdx.x][threadIdx.y]);
}

// ---------------- fp16 tensor-core GEMM ----------------
// C (nrows x 256) = act( A @ W + b ) [+ res]; A fp16, W fp16 [n][k], C fp16/fp32
struct GemmSet { const __half* WT; const float* b; void* C; };

#define TS 40  // smem stride in halves

template<bool RELU_OUT, bool ADD_RES, bool OUT_HALF>
__global__ __launch_bounds__(256)
void gemm_h(const __half* __restrict__ A,
            GemmSet s0, GemmSet s1, GemmSet s2,
            const float* __restrict__ res, int nrows)
{
    __shared__ __align__(16) __half As[128 * TS];
    __shared__ __align__(16) __half Ws[128 * TS];

    const GemmSet gs = (blockIdx.z == 0) ? s0 : (blockIdx.z == 1) ? s1 : s2;
    const __half* __restrict__ WT  = gs.WT;
    const float* __restrict__ bias = gs.b;

    const int tid  = threadIdx.x;
    const int lane = tid & 31;
    const int warp = tid >> 5;
    const int wm   = warp >> 2;
    const int wn   = warp & 3;
    const int m0   = blockIdx.x * 128;
    const int n0   = blockIdx.y * 128;
    const int g    = lane >> 2;
    const int t2   = (lane & 3) * 2;

    float acc[4][4][4];
#pragma unroll
    for (int i = 0; i < 4; i++)
#pragma unroll
        for (int j = 0; j < 4; j++)
#pragma unroll
            for (int k = 0; k < 4; k++) acc[i][j][k] = 0.f;

#pragma unroll 1
    for (int kt = 0; kt < 8; ++kt) {
        const int k0 = kt * 32;
        // A tile: 128 rows x 32 halves = 512 uint4
#pragma unroll
        for (int it = 0; it < 2; ++it) {
            int idx = it * 256 + tid;
            int row = idx >> 2;
            int kv  = idx & 3;
            int gm  = m0 + row;
            uint4 u = make_uint4(0u, 0u, 0u, 0u);
            if (gm < nrows) u = *(const uint4*)(A + (size_t)gm * 256 + k0 + kv * 8);
            *(uint4*)(&As[row * TS + kv * 8]) = u;
        }
        // W tile: 128 n-rows x 32 halves
#pragma unroll
        for (int it = 0; it < 2; ++it) {
            int idx = it * 256 + tid;
            int row = idx >> 2;
            int kv  = idx & 3;
            uint4 u = *(const uint4*)(WT + (size_t)(n0 + row) * 256 + k0 + kv * 8);
            *(uint4*)(&Ws[row * TS + kv * 8]) = u;
        }
        __syncthreads();

#pragma unroll
        for (int ks = 0; ks < 2; ++ks) {
            const int kk = ks * 16;
            unsigned af[4][4];
#pragma unroll
            for (int mt = 0; mt < 4; ++mt) {
                int r = wm * 64 + mt * 16 + g;
                af[mt][0] = *(const unsigned*)(&As[r * TS + kk + t2]);
                af[mt][1] = *(const unsigned*)(&As[(r + 8) * TS + kk + t2]);
                af[mt][2] = *(const unsigned*)(&As[r * TS + kk + t2 + 8]);
                af[mt][3] = *(const unsigned*)(&As[(r + 8) * TS + kk + t2 + 8]);
            }
            unsigned bf[4][2];
#pragma unroll
            for (int nt = 0; nt < 4; ++nt) {
                int n = wn * 32 + nt * 8 + g;
                bf[nt][0] = *(const unsigned*)(&Ws[n * TS + kk + t2]);
                bf[nt][1] = *(const unsigned*)(&Ws[n * TS + kk + t2 + 8]);
            }
#pragma unroll
            for (int mt = 0; mt < 4; ++mt)
#pragma unroll
                for (int nt = 0; nt < 4; ++nt)
                    mma_f16(acc[mt][nt], af[mt][0], af[mt][1], af[mt][2], af[mt][3],
                            bf[nt][0], bf[nt][1]);
        }
        __syncthreads();
    }

#pragma unroll
    for (int mt = 0; mt < 4; ++mt) {
#pragma unroll
        for (int nt = 0; nt < 4; ++nt) {
            int c  = n0 + wn * 32 + nt * 8 + t2;
            float2 b = *(const float2*)(bias + c);
            int r0 = m0 + wm * 64 + mt * 16 + g;
#pragma unroll
            for (int h = 0; h < 2; ++h) {
                int gm = r0 + h * 8;
                if (gm < nrows) {
                    float2 o;
                    o.x = acc[mt][nt][h * 2 + 0] + b.x;
                    o.y = acc[mt][nt][h * 2 + 1] + b.y;
                    if (RELU_OUT) { o.x = fmaxf(o.x, 0.f); o.y = fmaxf(o.y, 0.f); }
                    if (ADD_RES) {
                        float2 r = *(const float2*)(res + (size_t)gm * 256 + c);
                        o.x += r.x; o.y += r.y;
                    }
                    if (OUT_HALF) {
                        *(__half2*)((__half*)gs.C + (size_t)gm * 256 + c) =
                            __float22half2_rn(o);
                    } else {
                        *(float2*)((float*)gs.C + (size_t)gm * 256 + c) = o;
                    }
                }
            }
        }
    }
}

// ---------------- edge qk: 8 lanes per edge (lane = head), 4 edges/warp ----------------
__global__ __launch_bounds__(256)
void edge_qk(int m)
{
    __shared__ int smax;
    if (threadIdx.x == 0) smax = 0x80000000;
    __syncthreads();

    const int lane = threadIdx.x & 31;
    const int warp = (blockIdx.x * blockDim.x + threadIdx.x) >> 5;
    const int e = warp * 4 + (lane >> 3);
    const int h = lane & 7;

    float sv = -1e30f;
    if (e < m) {
        const int r = g_recv_s[e];
        const int s = g_send_s[e];
        const uint4* qp = (const uint4*)(g_Q + (size_t)r * 256 + h * 32);
        const uint4* kp = (const uint4*)(g_K + (size_t)s * 256 + h * 32);
        uint4 q0 = qp[0], q1 = qp[1], q2 = qp[2], q3 = qp[3];
        uint4 k0 = kp[0], k1 = kp[1], k2 = kp[2], k3 = kp[3];
        float acc = 0.f;
        const __half2 *qa, *ka;
#define DOT4(qq, kk) \
        qa = (const __half2*)&(qq); ka = (const __half2*)&(kk); \
        _Pragma("unroll") \
        for (int i = 0; i < 4; ++i) { \
            float2 qf = __half22float2(qa[i]); \
            float2 kf = __half22float2(ka[i]); \
            acc = fmaf(qf.x, kf.x, acc); \
            acc = fmaf(qf.y, kf.y, acc); \
        }
        DOT4(q0, k0) DOT4(q1, k1) DOT4(q2, k2) DOT4(q3, k3)
#undef DOT4
        g_att[(size_t)e * 8 + h] = acc;
        sv = acc;
    }
    float mx = sv;
#pragma unroll
    for (int off = 16; off; off >>= 1)
        mx = fmaxf(mx, __shfl_xor_sync(0xffffffffu, mx, off));
    if (lane == 0) atomicMax(&smax, f2ord(mx));
    __syncthreads();
    if (threadIdx.x == 0) atomicMax(&g_maxbits, smax);
}

// ---------------- per-node softmax + aggregation: warp per node ----------------
__global__ __launch_bounds__(256)
void node_msg(int n)
{
    __shared__ float sden[8][8];
    __shared__ float sscale;
    if (threadIdx.x == 0) sscale = 3.0f / ord2f(g_maxbits);
    __syncthreads();
    const float scale = sscale;

    const int warp = threadIdx.x >> 5;
    const int lane = threadIdx.x & 31;
    const int v = blockIdx.x * 8 + warp;
    if (v >= n) return;

    const int off = g_rowoff[v];
    const int end = g_rowoff[v + 1];

    // pass 1: per-head denominator
    float dsum = 0.f;
    for (int base = off; base < end; base += 4) {
        int e = base + (lane >> 3);
        float a = 0.f;
        if (e < end) a = __expf(g_att[(size_t)e * 8 + (lane & 7)] * scale);
        dsum += a;
    }
    dsum += __shfl_xor_sync(0xffffffffu, dsum, 8);
    dsum += __shfl_xor_sync(0xffffffffu, dsum, 16);
    if (lane < 8) sden[warp][lane] = dsum * 5.656854249492381f;  // fold sqrt(32)
    __syncwarp();

    // pass 2: weighted V aggregation, unrolled x2 (two gathers in flight)
    const int h = lane >> 2;
    const float inv = 1.0f / sden[warp][h];
    float acc[8] = {0.f, 0.f, 0.f, 0.f, 0.f, 0.f, 0.f, 0.f};

    for (int e = off; e < end; e += 2) {
        const bool two = (e + 1 < end);
        const int s0 = g_send_s[e];
        const int s1 = two ? g_send_s[e + 1] : s0;
        uint4 u0 = ((const uint4*)(g_V + (size_t)s0 * 256))[lane];
        uint4 u1 = ((const uint4*)(g_V + (size_t)s1 * 256))[lane];
        float w0 = __expf(g_att[(size_t)e * 8 + h] * scale) * inv;
        float w1 = two ? __expf(g_att[(size_t)(e + 1) * 8 + h] * scale) * inv : 0.f;
        const __half2* v0 = (const __half2*)&u0;
        const __half2* v1 = (const __half2*)&u1;
#pragma unroll
        for (int i = 0; i < 4; ++i) {
            float2 f0 = __half22float2(v0[i]);
            float2 f1 = __half22float2(v1[i]);
            acc[2 * i]     = fmaf(w0, f0.x, fmaf(w1, f1.x, acc[2 * i]));
            acc[2 * i + 1] = fmaf(w0, f0.y, fmaf(w1, f1.y, acc[2 * i + 1]));
        }
    }

    // store relu'd fp16 (8 halves = one uint4 per lane)
    __half2 h0 = __floats2half2_rn(fmaxf(acc[0], 0.f), fmaxf(acc[1], 0.f));
    __half2 h1 = __floats2half2_rn(fmaxf(acc[2], 0.f), fmaxf(acc[3], 0.f));
    __half2 h2 = __floats2half2_rn(fmaxf(acc[4], 0.f), fmaxf(acc[5], 0.f));
    __half2 h3 = __floats2half2_rn(fmaxf(acc[6], 0.f), fmaxf(acc[7], 0.f));
    __half2* Ap = (__half2*)(g_agg + (size_t)v * 256 + lane * 8);
    Ap[0] = h0; Ap[1] = h1; Ap[2] = h2; Ap[3] = h3;
}

// ---------------- launch ----------------
extern "C" void kernel_launch(void* const* d_in, const int* in_sizes, int n_in,
                              void* d_out, int out_size)
{
    const float* x    = (const float*)d_in[0];
    const int*   ei   = (const int*)d_in[1];
    const float* Wk   = (const float*)d_in[2];
    const float* bk   = (const float*)d_in[3];
    const float* Wq   = (const float*)d_in[4];
    const float* bq   = (const float*)d_in[5];
    const float* Wv   = (const float*)d_in[6];
    const float* bv   = (const float*)d_in[7];
    const float* Wagg = (const float*)d_in[8];
    const float* bagg = (const float*)d_in[9];
    const float* Wff  = (const float*)d_in[10];
    const float* bff  = (const float*)d_in[11];
    float* out = (float*)d_out;

    const int n = in_sizes[0] / 256;
    const int m = in_sizes[1] / 2;
    const int* recv = ei;
    const int* send = ei + m;

    __half *xhp, *Qp, *Kp, *Vp, *aggp, *h1p, *WTp;
    cudaGetSymbolAddress((void**)&xhp,  g_xh);
    cudaGetSymbolAddress((void**)&Qp,   g_Q);
    cudaGetSymbolAddress((void**)&Kp,   g_K);
    cudaGetSymbolAddress((void**)&Vp,   g_V);
    cudaGetSymbolAddress((void**)&aggp, g_agg);
    cudaGetSymbolAddress((void**)&h1p,  g_h1);
    cudaGetSymbolAddress((void**)&WTp,  g_WT);

    // conversions
    conv_x<<<(n * 64 + 255) / 256, 256>>>(x, n * 64);
    conv_w<<<dim3(8, 8, 5), dim3(32, 32)>>>(Wq, Wk, Wv, Wagg, Wff);

    // CSR build
    init_kernel<<<(n + 255) / 256, 256>>>(n);
    hist_kernel<<<(m + 255) / 256, 256>>>(recv, m);
    scan_kernel<<<1, 1024>>>(n);
    permute_kernel<<<(m + 255) / 256, 256>>>(recv, send, m);

    const int gx = (n + 127) / 128;

    GemmSet sq = {WTp,             bq, Qp};
    GemmSet sk = {WTp + 65536,     bk, Kp};
    GemmSet sv = {WTp + 2 * 65536, bv, Vp};
    gemm_h<false, false, true><<<dim3(gx, 2, 3), 256>>>(xhp, sq, sk, sv, nullptr, n);

    edge_qk<<<(m + 31) / 32, 256>>>(m);
    node_msg<<<(n + 7) / 8, 256>>>(n);

    GemmSet sa = {WTp + 3 * 65536, bagg, h1p};
    gemm_h<true, false, true><<<dim3(gx, 2, 1), 256>>>(aggp, sa, sa, sa, nullptr, n);
    GemmSet sf = {WTp + 4 * 65536, bff, out};
    gemm_h<true, true, false><<<dim3(gx, 2, 1), 256>>>(h1p, sf, sf, sf, x, n);
}

// round 7
// speedup vs baseline: 1.7547x; 1.2043x over previous
#include <cuda_runtime.h>
#include <cuda_fp16.h>
#include <math.h>

#define NMAX 50000
#define MMAX 800000
#define DD 256

// ---------------- scratch (static device globals; no allocation) ----------------
__device__ __align__(16) __half g_xh[(size_t)NMAX * DD];   // x in fp16 (GEMM A)
__device__ __align__(16) __half g_Q[(size_t)NMAX * DD];
__device__ __align__(16) __half g_K[(size_t)NMAX * DD];
__device__ __align__(16) __half g_V[(size_t)NMAX * DD];
__device__ __align__(16) __half g_agg[(size_t)NMAX * DD];  // relu'd messages (fp16)
__device__ __align__(16) __half g_h1[(size_t)NMAX * DD];   // relu'd hidden (fp16)
__device__ __align__(16) __half g_WT[5 * 65536];           // weights fp16, [n][k]
__device__ __align__(16) float  g_att[(size_t)MMAX * 8];   // qk logits (sorted order)
__device__ int g_hist[NMAX];
__device__ int g_cursor[NMAX];
__device__ int g_rowoff[NMAX + 1];
__device__ int g_send_s[MMAX];
__device__ int g_recv_s[MMAX];
__device__ int g_maxbits;

__device__ __forceinline__ int f2ord(float f) {
    int b = __float_as_int(f);
    return b >= 0 ? b : (b ^ 0x7FFFFFFF);
}
__device__ __forceinline__ float ord2f(int b) {
    return __int_as_float(b >= 0 ? b : (b ^ 0x7FFFFFFF));
}

__device__ __forceinline__ void mma_f16(float* c, unsigned a0, unsigned a1,
                                        unsigned a2, unsigned a3,
                                        unsigned b0, unsigned b1) {
    asm volatile(
        "mma.sync.aligned.m16n8k16.row.col.f32.f16.f16.f32 "
        "{%0,%1,%2,%3}, {%4,%5,%6,%7}, {%8,%9}, {%0,%1,%2,%3};"
        : "+f"(c[0]), "+f"(c[1]), "+f"(c[2]), "+f"(c[3])
        : "r"(a0), "r"(a1), "r"(a2), "r"(a3), "r"(b0), "r"(b1));
}

__device__ __forceinline__ void cp_async16(void* smem, const void* gmem) {
    unsigned sa = (unsigned)__cvta_generic_to_shared(smem);
    asm volatile("cp.async.cg.shared.global [%0], [%1], 16;" :: "r"(sa), "l"(gmem));
}
__device__ __forceinline__ void cp_async16_pred(void* smem, const void* gmem, bool p) {
    unsigned sa = (unsigned)__cvta_generic_to_shared(smem);
    int sz = p ? 16 : 0;
    asm volatile("cp.async.cg.shared.global [%0], [%1], 16, %2;"
                 :: "r"(sa), "l"(gmem), "r"(sz));
}
__device__ __forceinline__ void cp_commit() {
    asm volatile("cp.async.commit_group;");
}
template<int N>
__device__ __forceinline__ void cp_wait() {
    asm volatile("cp.async.wait_group %0;" :: "n"(N));
}

// ---------------- CSR build ----------------
__global__ void init_kernel(int n) {
    int i = blockIdx.x * blockDim.x + threadIdx.x;
    if (i < n) g_hist[i] = 0;
    if (i == 0) g_maxbits = 0x80000000;
}

__global__ void hist_kernel(const int* __restrict__ recv, int m) {
    int i = blockIdx.x * blockDim.x + threadIdx.x;
    if (i < m) atomicAdd(&g_hist[recv[i]], 1);
}

__global__ __launch_bounds__(1024)
void scan_kernel(int n) {
    __shared__ int ssum[1024];
    const int t = threadIdx.x;
    const int chunk = (n + 1023) >> 10;
    const int base = t * chunk;
    const int lim = min(base + chunk, n);
    int s = 0;
    for (int i = base; i < lim; ++i) s += g_hist[i];
    ssum[t] = s;
    __syncthreads();
    for (int off = 1; off < 1024; off <<= 1) {
        int v = (t >= off) ? ssum[t - off] : 0;
        __syncthreads();
        ssum[t] += v;
        __syncthreads();
    }
    int run = ssum[t] - s;
    for (int i = base; i < lim; ++i) {
        int c = g_hist[i];
        g_rowoff[i] = run;
        g_cursor[i] = run;
        run += c;
    }
    if (t == 1023) g_rowoff[n] = run;
}

__global__ void permute_kernel(const int* __restrict__ recv,
                               const int* __restrict__ send, int m) {
    int e = blockIdx.x * blockDim.x + threadIdx.x;
    if (e >= m) return;
    int r = recv[e];
    int pos = atomicAdd(&g_cursor[r], 1);
    g_send_s[pos] = send[e];
    g_recv_s[pos] = r;
}

// ---------------- conversions ----------------
__global__ void conv_x(const float* __restrict__ x, int n4) {
    int i = blockIdx.x * blockDim.x + threadIdx.x;
    if (i >= n4) return;
    float4 v = ((const float4*)x)[i];
    ((__half2*)g_xh)[2 * i]     = __floats2half2_rn(v.x, v.y);
    ((__half2*)g_xh)[2 * i + 1] = __floats2half2_rn(v.z, v.w);
}

__global__ void conv_w(const float* w0, const float* w1, const float* w2,
                       const float* w3, const float* w4) {
    __shared__ float t[32][33];
    const float* W = (blockIdx.z == 0) ? w0 : (blockIdx.z == 1) ? w1 :
                     (blockIdx.z == 2) ? w2 : (blockIdx.z == 3) ? w3 : w4;
    int k0 = blockIdx.y * 32, n0 = blockIdx.x * 32;
    t[threadIdx.y][threadIdx.x] = W[(size_t)(k0 + threadIdx.y) * 256 + n0 + threadIdx.x];
    __syncthreads();
    g_WT[(size_t)blockIdx.z * 65536 + (size_t)(n0 + threadIdx.y) * 256 + k0 + threadIdx.x] =
        __float2half_rn(t[threadIdx.x][threadIdx.y]);
}

// ---------------- fp16 tensor-core GEMM, cp.async double-buffered ----------------
struct GemmSet { const __half* WT; const float* b; void* C; };

#define TS 40  // smem stride in halves

template<bool RELU_OUT, bool ADD_RES, bool OUT_HALF>
__global__ __launch_bounds__(256)
void gemm_h(const __half* __restrict__ A,
            GemmSet s0, GemmSet s1, GemmSet s2,
            const float* __restrict__ res, int nrows)
{
    __shared__ __align__(16) __half As[2][128 * TS];
    __shared__ __align__(16) __half Ws[2][128 * TS];

    const GemmSet gs = (blockIdx.z == 0) ? s0 : (blockIdx.z == 1) ? s1 : s2;
    const __half* __restrict__ WT  = gs.WT;
    const float* __restrict__ bias = gs.b;

    const int tid  = threadIdx.x;
    const int lane = tid & 31;
    const int warp = tid >> 5;
    const int wm   = warp >> 2;
    const int wn   = warp & 3;
    const int m0   = blockIdx.x * 128;
    const int n0   = blockIdx.y * 128;
    const int g    = lane >> 2;
    const int t2   = (lane & 3) * 2;

    const int lrow = tid >> 2;   // 0..63 (loader row base)
    const int lkv  = tid & 3;

    float acc[4][4][4];
#pragma unroll
    for (int i = 0; i < 4; i++)
#pragma unroll
        for (int j = 0; j < 4; j++)
#pragma unroll
            for (int k = 0; k < 4; k++) acc[i][j][k] = 0.f;

    // async tile loader: A rows [m0,m0+128), W rows [n0,n0+128), k window [k0,k0+32)
    auto load_tiles = [&](int st, int k0) {
#pragma unroll
        for (int it = 0; it < 2; ++it) {
            int row = it * 64 + lrow;
            int gm  = m0 + row;
            bool ok = gm < nrows;
            const __half* src = A + (size_t)(ok ? gm : 0) * 256 + k0 + lkv * 8;
            cp_async16_pred(&As[st][row * TS + lkv * 8], src, ok);
        }
#pragma unroll
        for (int it = 0; it < 2; ++it) {
            int row = it * 64 + lrow;
            cp_async16(&Ws[st][row * TS + lkv * 8],
                       WT + (size_t)(n0 + row) * 256 + k0 + lkv * 8);
        }
    };

    load_tiles(0, 0);
    cp_commit();

#pragma unroll 1
    for (int kt = 0; kt < 8; ++kt) {
        const int cur = kt & 1;
        if (kt < 7) {
            load_tiles(cur ^ 1, (kt + 1) * 32);
            cp_commit();
            cp_wait<1>();
        } else {
            cp_wait<0>();
        }
        __syncthreads();

        const __half* Ab = As[cur];
        const __half* Wb = Ws[cur];
#pragma unroll
        for (int ks = 0; ks < 2; ++ks) {
            const int kk = ks * 16;
            unsigned af[4][4];
#pragma unroll
            for (int mt = 0; mt < 4; ++mt) {
                int r = wm * 64 + mt * 16 + g;
                af[mt][0] = *(const unsigned*)(&Ab[r * TS + kk + t2]);
                af[mt][1] = *(const unsigned*)(&Ab[(r + 8) * TS + kk + t2]);
                af[mt][2] = *(const unsigned*)(&Ab[r * TS + kk + t2 + 8]);
                af[mt][3] = *(const unsigned*)(&Ab[(r + 8) * TS + kk + t2 + 8]);
            }
            unsigned bf[4][2];
#pragma unroll
            for (int nt = 0; nt < 4; ++nt) {
                int n = wn * 32 + nt * 8 + g;
                bf[nt][0] = *(const unsigned*)(&Wb[n * TS + kk + t2]);
                bf[nt][1] = *(const unsigned*)(&Wb[n * TS + kk + t2 + 8]);
            }
#pragma unroll
            for (int mt = 0; mt < 4; ++mt)
#pragma unroll
                for (int nt = 0; nt < 4; ++nt)
                    mma_f16(acc[mt][nt], af[mt][0], af[mt][1], af[mt][2], af[mt][3],
                            bf[nt][0], bf[nt][1]);
        }
        __syncthreads();
    }

#pragma unroll
    for (int mt = 0; mt < 4; ++mt) {
#pragma unroll
        for (int nt = 0; nt < 4; ++nt) {
            int c  = n0 + wn * 32 + nt * 8 + t2;
            float2 b = *(const float2*)(bias + c);
            int r0 = m0 + wm * 64 + mt * 16 + g;
#pragma unroll
            for (int h = 0; h < 2; ++h) {
                int gm = r0 + h * 8;
                if (gm < nrows) {
                    float2 o;
                    o.x = acc[mt][nt][h * 2 + 0] + b.x;
                    o.y = acc[mt][nt][h * 2 + 1] + b.y;
                    if (RELU_OUT) { o.x = fmaxf(o.x, 0.f); o.y = fmaxf(o.y, 0.f); }
                    if (ADD_RES) {
                        float2 r = *(const float2*)(res + (size_t)gm * 256 + c);
                        o.x += r.x; o.y += r.y;
                    }
                    if (OUT_HALF) {
                        *(__half2*)((__half*)gs.C + (size_t)gm * 256 + c) =
                            __float22half2_rn(o);
                    } else {
                        *(float2*)((float*)gs.C + (size_t)gm * 256 + c) = o;
                    }
                }
            }
        }
    }
}

// ---------------- edge qk: 8 lanes per edge (lane = head), 4 edges/warp ----------------
__global__ __launch_bounds__(256)
void edge_qk(int m)
{
    __shared__ int smax;
    if (threadIdx.x == 0) smax = 0x80000000;
    __syncthreads();

    const int lane = threadIdx.x & 31;
    const int warp = (blockIdx.x * blockDim.x + threadIdx.x) >> 5;
    const int e = warp * 4 + (lane >> 3);
    const int h = lane & 7;

    float sv = -1e30f;
    if (e < m) {
        const int r = g_recv_s[e];
        const int s = g_send_s[e];
        const uint4* qp = (const uint4*)(g_Q + (size_t)r * 256 + h * 32);
        const uint4* kp = (const uint4*)(g_K + (size_t)s * 256 + h * 32);
        uint4 q0 = qp[0], q1 = qp[1], q2 = qp[2], q3 = qp[3];
        uint4 k0 = kp[0], k1 = kp[1], k2 = kp[2], k3 = kp[3];
        float acc = 0.f;
        const __half2 *qa, *ka;
#define DOT4(qq, kk) \
        qa = (const __half2*)&(qq); ka = (const __half2*)&(kk); \
        _Pragma("unroll") \
        for (int i = 0; i < 4; ++i) { \
            float2 qf = __half22float2(qa[i]); \
            float2 kf = __half22float2(ka[i]); \
            acc = fmaf(qf.x, kf.x, acc); \
            acc = fmaf(qf.y, kf.y, acc); \
        }
        DOT4(q0, k0) DOT4(q1, k1) DOT4(q2, k2) DOT4(q3, k3)
#undef DOT4
        g_att[(size_t)e * 8 + h] = acc;
        sv = acc;
    }
    float mx = sv;
#pragma unroll
    for (int off = 16; off; off >>= 1)
        mx = fmaxf(mx, __shfl_xor_sync(0xffffffffu, mx, off));
    if (lane == 0) atomicMax(&smax, f2ord(mx));
    __syncthreads();
    if (threadIdx.x == 0) atomicMax(&g_maxbits, smax);
}

// ---------------- per-node softmax + aggregation: warp per node ----------------
__global__ __launch_bounds__(256)
void node_msg(int n)
{
    __shared__ float sden[8][8];
    __shared__ float sscale;
    if (threadIdx.x == 0) sscale = 3.0f / ord2f(g_maxbits);
    __syncthreads();
    const float scale = sscale;

    const int warp = threadIdx.x >> 5;
    const int lane = threadIdx.x & 31;
    const int v = blockIdx.x * 8 + warp;
    if (v >= n) return;

    const int off = g_rowoff[v];
    const int end = g_rowoff[v + 1];

    float dsum = 0.f;
    for (int base = off; base < end; base += 4) {
        int e = base + (lane >> 3);
        float a = 0.f;
        if (e < end) a = __expf(g_att[(size_t)e * 8 + (lane & 7)] * scale);
        dsum += a;
    }
    dsum += __shfl_xor_sync(0xffffffffu, dsum, 8);
    dsum += __shfl_xor_sync(0xffffffffu, dsum, 16);
    if (lane < 8) sden[warp][lane] = dsum * 5.656854249492381f;  // fold sqrt(32)
    __syncwarp();

    const int h = lane >> 2;
    const float inv = 1.0f / sden[warp][h];
    float acc[8] = {0.f, 0.f, 0.f, 0.f, 0.f, 0.f, 0.f, 0.f};

    for (int e = off; e < end; e += 2) {
        const bool two = (e + 1 < end);
        const int s0 = g_send_s[e];
        const int s1 = two ? g_send_s[e + 1] : s0;
        uint4 u0 = ((const uint4*)(g_V + (size_t)s0 * 256))[lane];
        uint4 u1 = ((const uint4*)(g_V + (size_t)s1 * 256))[lane];
        float w0 = __expf(g_att[(size_t)e * 8 + h] * scale) * inv;
        float w1 = two ? __expf(g_att[(size_t)(e + 1) * 8 + h] * scale) * inv : 0.f;
        const __half2* v0 = (const __half2*)&u0;
        const __half2* v1 = (const __half2*)&u1;
#pragma unroll
        for (int i = 0; i < 4; ++i) {
            float2 f0 = __half22float2(v0[i]);
            float2 f1 = __half22float2(v1[i]);
            acc[2 * i]     = fmaf(w0, f0.x, fmaf(w1, f1.x, acc[2 * i]));
            acc[2 * i + 1] = fmaf(w0, f0.y, fmaf(w1, f1.y, acc[2 * i + 1]));
        }
    }

    __half2 h0 = __floats2half2_rn(fmaxf(acc[0], 0.f), fmaxf(acc[1], 0.f));
    __half2 h1 = __floats2half2_rn(fmaxf(acc[2], 0.f), fmaxf(acc[3], 0.f));
    __half2 h2 = __floats2half2_rn(fmaxf(acc[4], 0.f), fmaxf(acc[5], 0.f));
    __half2 h3 = __floats2half2_rn(fmaxf(acc[6], 0.f), fmaxf(acc[7], 0.f));
    __half2* Ap = (__half2*)(g_agg + (size_t)v * 256 + lane * 8);
    Ap[0] = h0; Ap[1] = h1; Ap[2] = h2; Ap[3] = h3;
}

// ---------------- side stream / events (created once, before any capture) ----------------
struct Aux {
    cudaStream_t s2;
    cudaEvent_t evFork, evConv, evCSR, evV;
    Aux() {
        cudaStreamCreateWithFlags(&s2, cudaStreamNonBlocking);
        cudaEventCreateWithFlags(&evFork, cudaEventDisableTiming);
        cudaEventCreateWithFlags(&evConv, cudaEventDisableTiming);
        cudaEventCreateWithFlags(&evCSR,  cudaEventDisableTiming);
        cudaEventCreateWithFlags(&evV,    cudaEventDisableTiming);
    }
};
static Aux g_aux;

// ---------------- launch ----------------
extern "C" void kernel_launch(void* const* d_in, const int* in_sizes, int n_in,
                              void* d_out, int out_size)
{
    const float* x    = (const float*)d_in[0];
    const int*   ei   = (const int*)d_in[1];
    const float* Wk   = (const float*)d_in[2];
    const float* bk   = (const float*)d_in[3];
    const float* Wq   = (const float*)d_in[4];
    const float* bq   = (const float*)d_in[5];
    const float* Wv   = (const float*)d_in[6];
    const float* bv   = (const float*)d_in[7];
    const float* Wagg = (const float*)d_in[8];
    const float* bagg = (const float*)d_in[9];
    const float* Wff  = (const float*)d_in[10];
    const float* bff  = (const float*)d_in[11];
    float* out = (float*)d_out;

    const int n = in_sizes[0] / 256;
    const int m = in_sizes[1] / 2;
    const int* recv = ei;
    const int* send = ei + m;

    __half *xhp, *Qp, *Kp, *Vp, *aggp, *h1p, *WTp;
    cudaGetSymbolAddress((void**)&xhp,  g_xh);
    cudaGetSymbolAddress((void**)&Qp,   g_Q);
    cudaGetSymbolAddress((void**)&Kp,   g_K);
    cudaGetSymbolAddress((void**)&Vp,   g_V);
    cudaGetSymbolAddress((void**)&aggp, g_agg);
    cudaGetSymbolAddress((void**)&h1p,  g_h1);
    cudaGetSymbolAddress((void**)&WTp,  g_WT);

    cudaStream_t s2 = g_aux.s2;
    const int gx = (n + 127) / 128;

    // fork side branch
    cudaEventRecord(g_aux.evFork, 0);
    cudaStreamWaitEvent(s2, g_aux.evFork, 0);

    // side: CSR build
    init_kernel<<<(n + 255) / 256, 256, 0, s2>>>(n);
    hist_kernel<<<(m + 255) / 256, 256, 0, s2>>>(recv, m);
    scan_kernel<<<1, 1024, 0, s2>>>(n);
    permute_kernel<<<(m + 255) / 256, 256, 0, s2>>>(recv, send, m);
    cudaEventRecord(g_aux.evCSR, s2);

    // main: conversions
    conv_x<<<(n * 64 + 255) / 256, 256>>>(x, n * 64);
    conv_w<<<dim3(8, 8, 5), dim3(32, 32)>>>(Wq, Wk, Wv, Wagg, Wff);
    cudaEventRecord(g_aux.evConv, 0);

    // side: V projection (after conversions + CSR chain on s2)
    cudaStreamWaitEvent(s2, g_aux.evConv, 0);
    GemmSet sv = {WTp + 2 * 65536, bv, Vp};
    gemm_h<false, false, true><<<dim3(gx, 2, 1), 256, 0, s2>>>(xhp, sv, sv, sv, nullptr, n);
    cudaEventRecord(g_aux.evV, s2);

    // main: Q/K projections
    GemmSet sq = {WTp,         bq, Qp};
    GemmSet sk = {WTp + 65536, bk, Kp};
    gemm_h<false, false, true><<<dim3(gx, 2, 2), 256>>>(xhp, sq, sk, sk, nullptr, n);

    // join CSR, then edge logits
    cudaStreamWaitEvent(0, g_aux.evCSR, 0);
    edge_qk<<<(m + 31) / 32, 256>>>(m);

    // join V, then aggregation
    cudaStreamWaitEvent(0, g_aux.evV, 0);
    node_msg<<<(n + 7) / 8, 256>>>(n);

    GemmSet sa = {WTp + 3 * 65536, bagg, h1p};
    gemm_h<true, false, true><<<dim3(gx, 2, 1), 256>>>(aggp, sa, sa, sa, nullptr, n);
    GemmSet sf = {WTp + 4 * 65536, bff, out};
    gemm_h<true, true, false><<<dim3(gx, 2, 1), 256>>>(h1p, sf, sf, sf, x, n);
}

// round 8
// speedup vs baseline: 2.0892x; 1.1906x over previous
#include <cuda_runtime.h>
#include <cuda_fp16.h>
#include <math.h>

#define NMAX 50000
#define MMAX 800000
#define DD 256

// ---------------- scratch (static device globals; no allocation) ----------------
__device__ __align__(16) __half g_xh[(size_t)NMAX * DD];   // x in fp16 (GEMM A)
__device__ __align__(16) __half g_Q[(size_t)NMAX * DD];
__device__ __align__(16) __half g_K[(size_t)NMAX * DD];
__device__ __align__(16) __half g_V[(size_t)NMAX * DD];
__device__ __align__(16) __half g_agg[(size_t)NMAX * DD];  // relu'd messages (fp16)
__device__ __align__(16) __half g_h1[(size_t)NMAX * DD];   // relu'd hidden (fp16)
__device__ __align__(16) __half g_WT[5 * 65536];           // weights fp16, [n][k]
__device__ __align__(16) float  g_att[(size_t)MMAX * 8];   // qk logits (CSR edge order)
__device__ int g_hist[NMAX];
__device__ int g_cursor[NMAX];
__device__ int g_rowoff[NMAX + 1];
__device__ int g_send_s[MMAX];
__device__ int g_maxbits;

__device__ __forceinline__ int f2ord(float f) {
    int b = __float_as_int(f);
    return b >= 0 ? b : (b ^ 0x7FFFFFFF);
}
__device__ __forceinline__ float ord2f(int b) {
    return __int_as_float(b >= 0 ? b : (b ^ 0x7FFFFFFF));
}

__device__ __forceinline__ void mma_f16(float* c, unsigned a0, unsigned a1,
                                        unsigned a2, unsigned a3,
                                        unsigned b0, unsigned b1) {
    asm volatile(
        "mma.sync.aligned.m16n8k16.row.col.f32.f16.f16.f32 "
        "{%0,%1,%2,%3}, {%4,%5,%6,%7}, {%8,%9}, {%0,%1,%2,%3};"
        : "+f"(c[0]), "+f"(c[1]), "+f"(c[2]), "+f"(c[3])
        : "r"(a0), "r"(a1), "r"(a2), "r"(a3), "r"(b0), "r"(b1));
}

__device__ __forceinline__ void cp_async16(void* smem, const void* gmem) {
    unsigned sa = (unsigned)__cvta_generic_to_shared(smem);
    asm volatile("cp.async.cg.shared.global [%0], [%1], 16;" :: "r"(sa), "l"(gmem));
}
__device__ __forceinline__ void cp_async16_pred(void* smem, const void* gmem, bool p) {
    unsigned sa = (unsigned)__cvta_generic_to_shared(smem);
    int sz = p ? 16 : 0;
    asm volatile("cp.async.cg.shared.global [%0], [%1], 16, %2;"
                 :: "r"(sa), "l"(gmem), "r"(sz));
}
__device__ __forceinline__ void cp_commit() {
    asm volatile("cp.async.commit_group;");
}
template<int N>
__device__ __forceinline__ void cp_wait() {
    asm volatile("cp.async.wait_group %0;" :: "n"(N));
}

// ---------------- CSR build ----------------
__global__ void init_kernel(int n) {
    int i = blockIdx.x * blockDim.x + threadIdx.x;
    if (i < n) g_hist[i] = 0;
    if (i == 0) g_maxbits = 0x80000000;
}

__global__ void hist_kernel(const int* __restrict__ recv, int m) {
    int i = blockIdx.x * blockDim.x + threadIdx.x;
    if (i < m) atomicAdd(&g_hist[recv[i]], 1);
}

__global__ __launch_bounds__(1024)
void scan_kernel(int n) {
    __shared__ int ssum[1024];
    const int t = threadIdx.x;
    const int chunk = (n + 1023) >> 10;
    const int base = t * chunk;
    const int lim = min(base + chunk, n);
    int s = 0;
    for (int i = base; i < lim; ++i) s += g_hist[i];
    ssum[t] = s;
    __syncthreads();
    for (int off = 1; off < 1024; off <<= 1) {
        int v = (t >= off) ? ssum[t - off] : 0;
        __syncthreads();
        ssum[t] += v;
        __syncthreads();
    }
    int run = ssum[t] - s;
    for (int i = base; i < lim; ++i) {
        int c = g_hist[i];
        g_rowoff[i] = run;
        g_cursor[i] = run;
        run += c;
    }
    if (t == 1023) g_rowoff[n] = run;
}

__global__ void permute_kernel(const int* __restrict__ recv,
                               const int* __restrict__ send, int m) {
    int e = blockIdx.x * blockDim.x + threadIdx.x;
    if (e >= m) return;
    int r = recv[e];
    int pos = atomicAdd(&g_cursor[r], 1);
    g_send_s[pos] = send[e];
}

// ---------------- conversions ----------------
__global__ void conv_x(const float* __restrict__ x, int n4) {
    int i = blockIdx.x * blockDim.x + threadIdx.x;
    if (i >= n4) return;
    float4 v = ((const float4*)x)[i];
    ((__half2*)g_xh)[2 * i]     = __floats2half2_rn(v.x, v.y);
    ((__half2*)g_xh)[2 * i + 1] = __floats2half2_rn(v.z, v.w);
}

__global__ void conv_w(const float* w0, const float* w1, const float* w2,
                       const float* w3, const float* w4) {
    __shared__ float t[32][33];
    const float* W = (blockIdx.z == 0) ? w0 : (blockIdx.z == 1) ? w1 :
                     (blockIdx.z == 2) ? w2 : (blockIdx.z == 3) ? w3 : w4;
    int k0 = blockIdx.y * 32, n0 = blockIdx.x * 32;
    t[threadIdx.y][threadIdx.x] = W[(size_t)(k0 + threadIdx.y) * 256 + n0 + threadIdx.x];
    __syncthreads();
    g_WT[(size_t)blockIdx.z * 65536 + (size_t)(n0 + threadIdx.y) * 256 + k0 + threadIdx.x] =
        __float2half_rn(t[threadIdx.x][threadIdx.y]);
}

// ---------------- fp16 tensor-core GEMM, cp.async double-buffered ----------------
struct GemmSet { const __half* WT; const float* b; void* C; };

#define TS 40  // smem stride in halves

template<bool RELU_OUT, bool ADD_RES, bool OUT_HALF>
__global__ __launch_bounds__(256)
void gemm_h(const __half* __restrict__ A,
            GemmSet s0, GemmSet s1, GemmSet s2,
            const float* __restrict__ res, int nrows)
{
    __shared__ __align__(16) __half As[2][128 * TS];
    __shared__ __align__(16) __half Ws[2][128 * TS];

    const GemmSet gs = (blockIdx.z == 0) ? s0 : (blockIdx.z == 1) ? s1 : s2;
    const __half* __restrict__ WT  = gs.WT;
    const float* __restrict__ bias = gs.b;

    const int tid  = threadIdx.x;
    const int lane = tid & 31;
    const int warp = tid >> 5;
    const int wm   = warp >> 2;
    const int wn   = warp & 3;
    const int m0   = blockIdx.x * 128;
    const int n0   = blockIdx.y * 128;
    const int g    = lane >> 2;
    const int t2   = (lane & 3) * 2;

    const int lrow = tid >> 2;
    const int lkv  = tid & 3;

    float acc[4][4][4];
#pragma unroll
    for (int i = 0; i < 4; i++)
#pragma unroll
        for (int j = 0; j < 4; j++)
#pragma unroll
            for (int k = 0; k < 4; k++) acc[i][j][k] = 0.f;

    auto load_tiles = [&](int st, int k0) {
#pragma unroll
        for (int it = 0; it < 2; ++it) {
            int row = it * 64 + lrow;
            int gm  = m0 + row;
            bool ok = gm < nrows;
            const __half* src = A + (size_t)(ok ? gm : 0) * 256 + k0 + lkv * 8;
            cp_async16_pred(&As[st][row * TS + lkv * 8], src, ok);
        }
#pragma unroll
        for (int it = 0; it < 2; ++it) {
            int row = it * 64 + lrow;
            cp_async16(&Ws[st][row * TS + lkv * 8],
                       WT + (size_t)(n0 + row) * 256 + k0 + lkv * 8);
        }
    };

    load_tiles(0, 0);
    cp_commit();

#pragma unroll 1
    for (int kt = 0; kt < 8; ++kt) {
        const int cur = kt & 1;
        if (kt < 7) {
            load_tiles(cur ^ 1, (kt + 1) * 32);
            cp_commit();
            cp_wait<1>();
        } else {
            cp_wait<0>();
        }
        __syncthreads();

        const __half* Ab = As[cur];
        const __half* Wb = Ws[cur];
#pragma unroll
        for (int ks = 0; ks < 2; ++ks) {
            const int kk = ks * 16;
            unsigned af[4][4];
#pragma unroll
            for (int mt = 0; mt < 4; ++mt) {
                int r = wm * 64 + mt * 16 + g;
                af[mt][0] = *(const unsigned*)(&Ab[r * TS + kk + t2]);
                af[mt][1] = *(const unsigned*)(&Ab[(r + 8) * TS + kk + t2]);
                af[mt][2] = *(const unsigned*)(&Ab[r * TS + kk + t2 + 8]);
                af[mt][3] = *(const unsigned*)(&Ab[(r + 8) * TS + kk + t2 + 8]);
            }
            unsigned bf[4][2];
#pragma unroll
            for (int nt = 0; nt < 4; ++nt) {
                int n = wn * 32 + nt * 8 + g;
                bf[nt][0] = *(const unsigned*)(&Wb[n * TS + kk + t2]);
                bf[nt][1] = *(const unsigned*)(&Wb[n * TS + kk + t2 + 8]);
            }
#pragma unroll
            for (int mt = 0; mt < 4; ++mt)
#pragma unroll
                for (int nt = 0; nt < 4; ++nt)
                    mma_f16(acc[mt][nt], af[mt][0], af[mt][1], af[mt][2], af[mt][3],
                            bf[nt][0], bf[nt][1]);
        }
        __syncthreads();
    }

#pragma unroll
    for (int mt = 0; mt < 4; ++mt) {
#pragma unroll
        for (int nt = 0; nt < 4; ++nt) {
            int c  = n0 + wn * 32 + nt * 8 + t2;
            float2 b = *(const float2*)(bias + c);
            int r0 = m0 + wm * 64 + mt * 16 + g;
#pragma unroll
            for (int h = 0; h < 2; ++h) {
                int gm = r0 + h * 8;
                if (gm < nrows) {
                    float2 o;
                    o.x = acc[mt][nt][h * 2 + 0] + b.x;
                    o.y = acc[mt][nt][h * 2 + 1] + b.y;
                    if (RELU_OUT) { o.x = fmaxf(o.x, 0.f); o.y = fmaxf(o.y, 0.f); }
                    if (ADD_RES) {
                        float2 r = *(const float2*)(res + (size_t)gm * 256 + c);
                        o.x += r.x; o.y += r.y;
                    }
                    if (OUT_HALF) {
                        *(__half2*)((__half*)gs.C + (size_t)gm * 256 + c) =
                            __float22half2_rn(o);
                    } else {
                        *(float2*)((float*)gs.C + (size_t)gm * 256 + c) = o;
                    }
                }
            }
        }
    }
}

// ---------------- node qk: warp per node; Q in registers, K gathered per edge ----------------
__global__ __launch_bounds__(256)
void node_qk(int n)
{
    __shared__ int smax;
    if (threadIdx.x == 0) smax = 0x80000000;
    __syncthreads();

    const int warp = threadIdx.x >> 5;
    const int lane = threadIdx.x & 31;
    const int v = blockIdx.x * 8 + warp;
    const int h = lane >> 2;  // head for this lane's 8-dim slice

    float mx = -1e30f;
    if (v < n) {
        const int off = g_rowoff[v];
        const int end = g_rowoff[v + 1];

        // load Q[v] slice once: 8 halves -> 8 floats in registers
        uint4 qu = ((const uint4*)(g_Q + (size_t)v * 256))[lane];
        const __half2* qh = (const __half2*)&qu;
        float qf[8];
#pragma unroll
        for (int i = 0; i < 4; ++i) {
            float2 f = __half22float2(qh[i]);
            qf[2 * i] = f.x; qf[2 * i + 1] = f.y;
        }

        for (int e = off; e < end; e += 2) {
            const bool two = (e + 1 < end);
            const int s0 = g_send_s[e];
            const int s1 = two ? g_send_s[e + 1] : s0;
            uint4 k0 = ((const uint4*)(g_K + (size_t)s0 * 256))[lane];
            uint4 k1 = ((const uint4*)(g_K + (size_t)s1 * 256))[lane];
            const __half2* ka = (const __half2*)&k0;
            const __half2* kb = (const __half2*)&k1;
            float d0 = 0.f, d1 = 0.f;
#pragma unroll
            for (int i = 0; i < 4; ++i) {
                float2 fa = __half22float2(ka[i]);
                float2 fb = __half22float2(kb[i]);
                d0 = fmaf(qf[2 * i], fa.x, d0);
                d0 = fmaf(qf[2 * i + 1], fa.y, d0);
                d1 = fmaf(qf[2 * i], fb.x, d1);
                d1 = fmaf(qf[2 * i + 1], fb.y, d1);
            }
            // reduce within 4-lane head group
            d0 += __shfl_xor_sync(0xffffffffu, d0, 1);
            d0 += __shfl_xor_sync(0xffffffffu, d0, 2);
            d1 += __shfl_xor_sync(0xffffffffu, d1, 1);
            d1 += __shfl_xor_sync(0xffffffffu, d1, 2);
            if ((lane & 3) == 0) {
                g_att[(size_t)e * 8 + h] = d0;
                if (two) {
                    g_att[(size_t)(e + 1) * 8 + h] = d1;
                    mx = fmaxf(mx, fmaxf(d0, d1));
                } else {
                    mx = fmaxf(mx, d0);
                }
            }
        }
    }
#pragma unroll
    for (int off = 16; off; off >>= 1)
        mx = fmaxf(mx, __shfl_xor_sync(0xffffffffu, mx, off));
    if (lane == 0) atomicMax(&smax, f2ord(mx));
    __syncthreads();
    if (threadIdx.x == 0) atomicMax(&g_maxbits, smax);
}

// ---------------- per-node softmax + aggregation: warp per node ----------------
__global__ __launch_bounds__(256)
void node_msg(int n)
{
    __shared__ float sden[8][8];
    __shared__ float sscale;
    if (threadIdx.x == 0) sscale = 3.0f / ord2f(g_maxbits);
    __syncthreads();
    const float scale = sscale;

    const int warp = threadIdx.x >> 5;
    const int lane = threadIdx.x & 31;
    const int v = blockIdx.x * 8 + warp;
    if (v >= n) return;

    const int off = g_rowoff[v];
    const int end = g_rowoff[v + 1];

    float dsum = 0.f;
    for (int base = off; base < end; base += 4) {
        int e = base + (lane >> 3);
        float a = 0.f;
        if (e < end) a = __expf(g_att[(size_t)e * 8 + (lane & 7)] * scale);
        dsum += a;
    }
    dsum += __shfl_xor_sync(0xffffffffu, dsum, 8);
    dsum += __shfl_xor_sync(0xffffffffu, dsum, 16);
    if (lane < 8) sden[warp][lane] = dsum * 5.656854249492381f;  // fold sqrt(32)
    __syncwarp();

    const int h = lane >> 2;
    const float inv = 1.0f / sden[warp][h];
    float acc[8] = {0.f, 0.f, 0.f, 0.f, 0.f, 0.f, 0.f, 0.f};

    for (int e = off; e < end; e += 2) {
        const bool two = (e + 1 < end);
        const int s0 = g_send_s[e];
        const int s1 = two ? g_send_s[e + 1] : s0;
        uint4 u0 = ((const uint4*)(g_V + (size_t)s0 * 256))[lane];
        uint4 u1 = ((const uint4*)(g_V + (size_t)s1 * 256))[lane];
        float w0 = __expf(g_att[(size_t)e * 8 + h] * scale) * inv;
        float w1 = two ? __expf(g_att[(size_t)(e + 1) * 8 + h] * scale) * inv : 0.f;
        const __half2* v0 = (const __half2*)&u0;
        const __half2* v1 = (const __half2*)&u1;
#pragma unroll
        for (int i = 0; i < 4; ++i) {
            float2 f0 = __half22float2(v0[i]);
            float2 f1 = __half22float2(v1[i]);
            acc[2 * i]     = fmaf(w0, f0.x, fmaf(w1, f1.x, acc[2 * i]));
            acc[2 * i + 1] = fmaf(w0, f0.y, fmaf(w1, f1.y, acc[2 * i + 1]));
        }
    }

    __half2 h0 = __floats2half2_rn(fmaxf(acc[0], 0.f), fmaxf(acc[1], 0.f));
    __half2 h1 = __floats2half2_rn(fmaxf(acc[2], 0.f), fmaxf(acc[3], 0.f));
    __half2 h2 = __floats2half2_rn(fmaxf(acc[4], 0.f), fmaxf(acc[5], 0.f));
    __half2 h3 = __floats2half2_rn(fmaxf(acc[6], 0.f), fmaxf(acc[7], 0.f));
    __half2* Ap = (__half2*)(g_agg + (size_t)v * 256 + lane * 8);
    Ap[0] = h0; Ap[1] = h1; Ap[2] = h2; Ap[3] = h3;
}

// ---------------- side stream / events (created once, before any capture) ----------------
struct Aux {
    cudaStream_t s2;
    cudaEvent_t evFork, evConv, evCSR, evV;
    Aux() {
        cudaStreamCreateWithFlags(&s2, cudaStreamNonBlocking);
        cudaEventCreateWithFlags(&evFork, cudaEventDisableTiming);
        cudaEventCreateWithFlags(&evConv, cudaEventDisableTiming);
        cudaEventCreateWithFlags(&evCSR,  cudaEventDisableTiming);
        cudaEventCreateWithFlags(&evV,    cudaEventDisableTiming);
    }
};
static Aux g_aux;

// ---------------- launch ----------------
extern "C" void kernel_launch(void* const* d_in, const int* in_sizes, int n_in,
                              void* d_out, int out_size)
{
    const float* x    = (const float*)d_in[0];
    const int*   ei   = (const int*)d_in[1];
    const float* Wk   = (const float*)d_in[2];
    const float* bk   = (const float*)d_in[3];
    const float* Wq   = (const float*)d_in[4];
    const float* bq   = (const float*)d_in[5];
    const float* Wv   = (const float*)d_in[6];
    const float* bv   = (const float*)d_in[7];
    const float* Wagg = (const float*)d_in[8];
    const float* bagg = (const float*)d_in[9];
    const float* Wff  = (const float*)d_in[10];
    const float* bff  = (const float*)d_in[11];
    float* out = (float*)d_out;

    const int n = in_sizes[0] / 256;
    const int m = in_sizes[1] / 2;
    const int* recv = ei;
    const int* send = ei + m;

    __half *xhp, *Qp, *Kp, *Vp, *aggp, *h1p, *WTp;
    cudaGetSymbolAddress((void**)&xhp,  g_xh);
    cudaGetSymbolAddress((void**)&Qp,   g_Q);
    cudaGetSymbolAddress((void**)&Kp,   g_K);
    cudaGetSymbolAddress((void**)&Vp,   g_V);
    cudaGetSymbolAddress((void**)&aggp, g_agg);
    cudaGetSymbolAddress((void**)&h1p,  g_h1);
    cudaGetSymbolAddress((void**)&WTp,  g_WT);

    cudaStream_t s2 = g_aux.s2;
    const int gx = (n + 127) / 128;

    // fork side branch
    cudaEventRecord(g_aux.evFork, 0);
    cudaStreamWaitEvent(s2, g_aux.evFork, 0);

    // side: CSR build
    init_kernel<<<(n + 255) / 256, 256, 0, s2>>>(n);
    hist_kernel<<<(m + 255) / 256, 256, 0, s2>>>(recv, m);
    scan_kernel<<<1, 1024, 0, s2>>>(n);
    permute_kernel<<<(m + 255) / 256, 256, 0, s2>>>(recv, send, m);
    cudaEventRecord(g_aux.evCSR, s2);

    // main: conversions
    conv_x<<<(n * 64 + 255) / 256, 256>>>(x, n * 64);
    conv_w<<<dim3(8, 8, 5), dim3(32, 32)>>>(Wq, Wk, Wv, Wagg, Wff);
    cudaEventRecord(g_aux.evConv, 0);

    // side: V projection (after conversions + CSR chain on s2)
    cudaStreamWaitEvent(s2, g_aux.evConv, 0);
    GemmSet sv = {WTp + 2 * 65536, bv, Vp};
    gemm_h<false, false, true><<<dim3(gx, 2, 1), 256, 0, s2>>>(xhp, sv, sv, sv, nullptr, n);
    cudaEventRecord(g_aux.evV, s2);

    // main: Q/K projections
    GemmSet sq = {WTp,         bq, Qp};
    GemmSet sk = {WTp + 65536, bk, Kp};
    gemm_h<false, false, true><<<dim3(gx, 2, 2), 256>>>(xhp, sq, sk, sk, nullptr, n);

    // join CSR, then node-centric edge logits
    cudaStreamWaitEvent(0, g_aux.evCSR, 0);
    node_qk<<<(n + 7) / 8, 256>>>(n);

    // join V, then aggregation
    cudaStreamWaitEvent(0, g_aux.evV, 0);
    node_msg<<<(n + 7) / 8, 256>>>(n);

    GemmSet sa = {WTp + 3 * 65536, bagg, h1p};
    gemm_h<true, false, true><<<dim3(gx, 2, 1), 256>>>(aggp, sa, sa, sa, nullptr, n);
    GemmSet sf = {WTp + 4 * 65536, bff, out};
    gemm_h<true, true, false><<<dim3(gx, 2, 1), 256>>>(h1p, sf, sf, sf, x, n);
}